// round 5
// baseline (speedup 1.0000x reference)
#include <cuda_runtime.h>
#include <math.h>

// Problem constants
#define BATCH 4
#define SEQ   2048
#define DM    1024
#define NH    16
#define HD    64
#define NTOK  (BATCH * SEQ)   // 8192
#define LN_EPS 1e-6f

// ---------------------------------------------------------------------------
// Scratch (device globals: no allocation allowed in kernel_launch)
// ---------------------------------------------------------------------------
__device__ float g_q[NTOK * DM];     // [B,H,S,HD]
__device__ float g_k[NTOK * DM];     // [B,H,S,HD]
__device__ float g_v[NTOK * DM];     // [B,H,S,HD]
__device__ float g_attn[NTOK * DM];  // [B,S,DM]
__device__ float g_proj[NTOK * DM];  // [B,S,DM]

// ---------------------------------------------------------------------------
// SGEMM: C[M=8192, N=1024] = A[8192,1024] @ W[1024,1024] + bias
// 128x128 tile, BK=8, 256 threads, 8x8 register blocking.
// SPLIT=1: write C into [B,H,S,HD] head-split layout. SPLIT=0: row-major.
// ---------------------------------------------------------------------------
#define GBM 128
#define GBN 128
#define GBK 8
#define AS_STRIDE 132   // pad to avoid STS bank conflicts

template <int SPLIT>
__global__ __launch_bounds__(256) void gemm128(
    const float* __restrict__ A, const float* __restrict__ W,
    const float* __restrict__ bias, float* __restrict__ C)
{
    __shared__ float As[GBK * AS_STRIDE];  // stored [k][m]
    __shared__ float Bs[GBK * AS_STRIDE];  // stored [k][n]

    const int tid = threadIdx.x;
    const int tx = tid & 15;       // 0..15 -> n
    const int ty = tid >> 4;       // 0..15 -> m
    const int row0 = blockIdx.y * GBM;
    const int col0 = blockIdx.x * GBN;

    // A tile global load mapping: thread -> (row, 4 consecutive k)
    const int a_row = tid >> 1;            // 0..127
    const int a_k   = (tid & 1) * 4;       // 0 or 4
    // B tile: thread -> (k row, 4 consecutive n)
    const int b_k   = tid >> 5;            // 0..7
    const int b_n   = (tid & 31) * 4;      // 0..124

    float acc[8][8];
    #pragma unroll
    for (int i = 0; i < 8; i++)
        #pragma unroll
        for (int j = 0; j < 8; j++) acc[i][j] = 0.0f;

    for (int k0 = 0; k0 < DM; k0 += GBK) {
        float4 a4 = *(const float4*)(A + (size_t)(row0 + a_row) * DM + k0 + a_k);
        As[(a_k + 0) * AS_STRIDE + a_row] = a4.x;
        As[(a_k + 1) * AS_STRIDE + a_row] = a4.y;
        As[(a_k + 2) * AS_STRIDE + a_row] = a4.z;
        As[(a_k + 3) * AS_STRIDE + a_row] = a4.w;
        *(float4*)(&Bs[b_k * AS_STRIDE + b_n]) =
            *(const float4*)(W + (size_t)(k0 + b_k) * DM + col0 + b_n);
        __syncthreads();

        #pragma unroll
        for (int k = 0; k < GBK; k++) {
            float a[8], b[8];
            *(float4*)(a)     = *(float4*)(&As[k * AS_STRIDE + ty * 8]);
            *(float4*)(a + 4) = *(float4*)(&As[k * AS_STRIDE + ty * 8 + 4]);
            *(float4*)(b)     = *(float4*)(&Bs[k * AS_STRIDE + tx * 8]);
            *(float4*)(b + 4) = *(float4*)(&Bs[k * AS_STRIDE + tx * 8 + 4]);
            #pragma unroll
            for (int i = 0; i < 8; i++)
                #pragma unroll
                for (int j = 0; j < 8; j++)
                    acc[i][j] = fmaf(a[i], b[j], acc[i][j]);
        }
        __syncthreads();
    }

    // Epilogue
    #pragma unroll
    for (int i = 0; i < 8; i++) {
        const int r = row0 + ty * 8 + i;
        const int bb = r / SEQ, ss = r % SEQ;
        #pragma unroll
        for (int j = 0; j < 8; j++) {
            const int c = col0 + tx * 8 + j;
            const float val = acc[i][j] + bias[c];
            if (SPLIT) {
                const int h = c >> 6, d = c & 63;
                C[(((size_t)(bb * NH + h) * SEQ) + ss) * HD + d] = val;
            } else {
                C[(size_t)r * DM + c] = val;
            }
        }
    }
}

// ---------------------------------------------------------------------------
// Flash attention: one block per (head-batch, 64-query tile).
// 256 threads: row = tid/4 (0..63 query rows), cg = tid%4 (16-col segment).
// Online softmax, fp32, K/V streamed through smem in 64-row tiles.
// ---------------------------------------------------------------------------
#define TS 64
#define TPAD 68
#define ATTN_SMEM (4 * TS * TPAD * (int)sizeof(float))  // Qs,Ks,Vs,Ps = 69632 B

__global__ __launch_bounds__(256) void attn_kernel(
    const float* __restrict__ Q, const float* __restrict__ K,
    const float* __restrict__ V, float* __restrict__ Out)
{
    extern __shared__ float smem[];
    float* Qs = smem;                 // [TS][TPAD]
    float* Ks = Qs + TS * TPAD;
    float* Vs = Ks + TS * TPAD;
    float* Ps = Vs + TS * TPAD;

    const int bh = blockIdx.y;            // 0..63
    const int b = bh / NH, h = bh % NH;
    const int q0 = blockIdx.x * TS;
    const float* Qb = Q + (size_t)bh * SEQ * HD;
    const float* Kb = K + (size_t)bh * SEQ * HD;
    const float* Vb = V + (size_t)bh * SEQ * HD;

    const int tid = threadIdx.x;
    const int row = tid >> 2;     // 0..63
    const int cg  = tid & 3;      // 0..3

    // Load Q tile (64x64 floats, as float4)
    for (int i = tid; i < TS * (HD / 4); i += 256) {
        const int r = i >> 4, c4 = (i & 15) * 4;
        *(float4*)&Qs[r * TPAD + c4] = *(const float4*)(Qb + (size_t)(q0 + r) * HD + c4);
    }

    float m = -1e30f, l = 0.0f;
    float o[16];
    #pragma unroll
    for (int i = 0; i < 16; i++) o[i] = 0.0f;

    for (int kv0 = 0; kv0 < SEQ; kv0 += TS) {
        __syncthreads();  // protect Ks/Vs from readers of previous tile
        for (int i = tid; i < TS * (HD / 4); i += 256) {
            const int r = i >> 4, c4 = (i & 15) * 4;
            *(float4*)&Ks[r * TPAD + c4] = *(const float4*)(Kb + (size_t)(kv0 + r) * HD + c4);
            *(float4*)&Vs[r * TPAD + c4] = *(const float4*)(Vb + (size_t)(kv0 + r) * HD + c4);
        }
        __syncthreads();

        // Scores for this thread's 16 kv columns
        float sc[16];
        #pragma unroll
        for (int jj = 0; jj < 16; jj++) {
            const int j = cg * 16 + jj;
            float4 a = make_float4(0.f, 0.f, 0.f, 0.f);
            #pragma unroll
            for (int d = 0; d < HD; d += 4) {
                float4 q4 = *(float4*)&Qs[row * TPAD + d];
                float4 k4 = *(float4*)&Ks[j * TPAD + d];
                a.x = fmaf(q4.x, k4.x, a.x);
                a.y = fmaf(q4.y, k4.y, a.y);
                a.z = fmaf(q4.z, k4.z, a.z);
                a.w = fmaf(q4.w, k4.w, a.w);
            }
            sc[jj] = (a.x + a.y + a.z + a.w) * 0.125f;  // 1/sqrt(64)
        }

        // Row max (16 local + shuffle among the 4 threads of this row)
        float mloc = sc[0];
        #pragma unroll
        for (int jj = 1; jj < 16; jj++) mloc = fmaxf(mloc, sc[jj]);
        mloc = fmaxf(mloc, __shfl_xor_sync(0xffffffffu, mloc, 1));
        mloc = fmaxf(mloc, __shfl_xor_sync(0xffffffffu, mloc, 2));
        const float mnew = fmaxf(m, mloc);
        const float corr = __expf(m - mnew);

        float psum = 0.0f;
        #pragma unroll
        for (int jj = 0; jj < 16; jj++) {
            const float p = __expf(sc[jj] - mnew);
            psum += p;
            Ps[row * TPAD + cg * 16 + jj] = p;
        }
        psum += __shfl_xor_sync(0xffffffffu, psum, 1);
        psum += __shfl_xor_sync(0xffffffffu, psum, 2);
        l = l * corr + psum;
        m = mnew;

        #pragma unroll
        for (int i = 0; i < 16; i++) o[i] *= corr;

        __syncwarp();  // Ps row is produced/consumed by the same 4 lanes (same warp)

        // O += P @ V over this tile (thread owns 16 depth cols: cg*16..)
        #pragma unroll
        for (int j = 0; j < TS; j++) {
            const float p = Ps[row * TPAD + j];
            #pragma unroll
            for (int d4 = 0; d4 < 4; d4++) {
                float4 v4 = *(float4*)&Vs[j * TPAD + cg * 16 + d4 * 4];
                o[d4 * 4 + 0] = fmaf(p, v4.x, o[d4 * 4 + 0]);
                o[d4 * 4 + 1] = fmaf(p, v4.y, o[d4 * 4 + 1]);
                o[d4 * 4 + 2] = fmaf(p, v4.z, o[d4 * 4 + 2]);
                o[d4 * 4 + 3] = fmaf(p, v4.w, o[d4 * 4 + 3]);
            }
        }
        __syncwarp();
    }

    const float inv = 1.0f / l;
    float* op = Out + ((size_t)(b * SEQ + q0 + row)) * DM + h * HD + cg * 16;
    #pragma unroll
    for (int d4 = 0; d4 < 4; d4++) {
        float4 r;
        r.x = o[d4 * 4 + 0] * inv;
        r.y = o[d4 * 4 + 1] * inv;
        r.z = o[d4 * 4 + 2] * inv;
        r.w = o[d4 * 4 + 3] * inv;
        *(float4*)(op + d4 * 4) = r;
    }
}

// ---------------------------------------------------------------------------
// Residual + LayerNorm: one block (256 threads) per token row; 4 floats/thread
// ---------------------------------------------------------------------------
__global__ __launch_bounds__(256) void ln_kernel(
    const float* __restrict__ X, const float* __restrict__ P,
    const float* __restrict__ gamma, const float* __restrict__ beta,
    float* __restrict__ out)
{
    const int r = blockIdx.x;
    const int t = threadIdx.x;
    const float4 x4 = ((const float4*)(X + (size_t)r * DM))[t];
    const float4 p4 = ((const float4*)(P + (size_t)r * DM))[t];
    float v0 = x4.x + p4.x, v1 = x4.y + p4.y, v2 = x4.z + p4.z, v3 = x4.w + p4.w;

    __shared__ float red[8];
    __shared__ float s_mu, s_rstd;

    // mean
    float s = v0 + v1 + v2 + v3;
    #pragma unroll
    for (int off = 16; off > 0; off >>= 1) s += __shfl_xor_sync(0xffffffffu, s, off);
    if ((t & 31) == 0) red[t >> 5] = s;
    __syncthreads();
    if (t == 0) {
        float tot = 0.f;
        #pragma unroll
        for (int i = 0; i < 8; i++) tot += red[i];
        s_mu = tot * (1.0f / DM);
    }
    __syncthreads();
    const float mu = s_mu;

    // variance
    float c0 = v0 - mu, c1 = v1 - mu, c2 = v2 - mu, c3 = v3 - mu;
    float sq = c0 * c0 + c1 * c1 + c2 * c2 + c3 * c3;
    #pragma unroll
    for (int off = 16; off > 0; off >>= 1) sq += __shfl_xor_sync(0xffffffffu, sq, off);
    if ((t & 31) == 0) red[t >> 5] = sq;
    __syncthreads();
    if (t == 0) {
        float tot = 0.f;
        #pragma unroll
        for (int i = 0; i < 8; i++) tot += red[i];
        s_rstd = rsqrtf(tot * (1.0f / DM) + LN_EPS);
    }
    __syncthreads();
    const float rstd = s_rstd;

    const float4 g4 = ((const float4*)gamma)[t];
    const float4 b4 = ((const float4*)beta)[t];
    float4 o4;
    o4.x = c0 * rstd * g4.x + b4.x;
    o4.y = c1 * rstd * g4.y + b4.y;
    o4.z = c2 * rstd * g4.z + b4.z;
    o4.w = c3 * rstd * g4.w + b4.w;
    ((float4*)(out + (size_t)r * DM))[t] = o4;
}

// ---------------------------------------------------------------------------
// Launch
// ---------------------------------------------------------------------------
extern "C" void kernel_launch(void* const* d_in, const int* in_sizes, int n_in,
                              void* d_out, int out_size)
{
    const float* x     = (const float*)d_in[0];
    const float* Wq    = (const float*)d_in[1];
    const float* bq    = (const float*)d_in[2];
    const float* Wk    = (const float*)d_in[3];
    const float* bk    = (const float*)d_in[4];
    const float* Wv    = (const float*)d_in[5];
    const float* bv    = (const float*)d_in[6];
    const float* Wo    = (const float*)d_in[7];
    const float* bo    = (const float*)d_in[8];
    const float* gamma = (const float*)d_in[9];
    const float* beta  = (const float*)d_in[10];
    float* out = (float*)d_out;

    float *q, *k, *v, *attn, *proj;
    cudaGetSymbolAddress((void**)&q,    g_q);
    cudaGetSymbolAddress((void**)&k,    g_k);
    cudaGetSymbolAddress((void**)&v,    g_v);
    cudaGetSymbolAddress((void**)&attn, g_attn);
    cudaGetSymbolAddress((void**)&proj, g_proj);

    dim3 ggrid(DM / GBN, NTOK / GBM);   // (8, 64)
    gemm128<1><<<ggrid, 256>>>(x, Wq, bq, q);
    gemm128<1><<<ggrid, 256>>>(x, Wk, bk, k);
    gemm128<1><<<ggrid, 256>>>(x, Wv, bv, v);

    cudaFuncSetAttribute(attn_kernel,
                         cudaFuncAttributeMaxDynamicSharedMemorySize, ATTN_SMEM);
    attn_kernel<<<dim3(SEQ / TS, BATCH * NH), 256, ATTN_SMEM>>>(q, k, v, attn);

    gemm128<0><<<ggrid, 256>>>(attn, Wo, bo, proj);

    ln_kernel<<<NTOK, 256>>>(x, proj, gamma, beta, out);
}

// round 6
// speedup vs baseline: 23.8110x; 23.8110x over previous
#include <cuda_runtime.h>
#include <cuda_fp16.h>
#include <math.h>

#define BATCH 4
#define SEQ   2048
#define DM    1024
#define NH    16
#define HD    64
#define NTOK  (BATCH * SEQ)   // 8192
#define LN_EPS 1e-6f

// ---------------------------------------------------------------------------
// Device-global scratch (no allocation allowed anywhere)
// ---------------------------------------------------------------------------
__device__ __half g_hx[NTOK * DM];            // x in fp16
__device__ __half g_hwq[DM * DM], g_hwk[DM * DM], g_hwv[DM * DM], g_hwo[DM * DM];
__device__ __half g_q[NTOK * DM];             // [B,H,S,HD] fp16 (pre-scaled by 1/8)
__device__ __half g_k[NTOK * DM];             // [B,H,S,HD]
__device__ __half g_v[NTOK * DM];             // [B,H,S,HD]
__device__ __half g_ah[NTOK * DM];            // attention out [B,S,DM] fp16
__device__ float  g_proj[NTOK * DM];          // O-projection out fp32

// ---------------------------------------------------------------------------
// PTX helpers
// ---------------------------------------------------------------------------
__device__ __forceinline__ unsigned smem_u32(const void* p) {
    return (unsigned)__cvta_generic_to_shared(p);
}
__device__ __forceinline__ void ldsm4(unsigned* r, unsigned a) {
    asm volatile("ldmatrix.sync.aligned.m8n8.x4.shared.b16 {%0,%1,%2,%3},[%4];"
                 : "=r"(r[0]), "=r"(r[1]), "=r"(r[2]), "=r"(r[3]) : "r"(a));
}
__device__ __forceinline__ void ldsm4t(unsigned* r, unsigned a) {
    asm volatile("ldmatrix.sync.aligned.m8n8.x4.trans.shared.b16 {%0,%1,%2,%3},[%4];"
                 : "=r"(r[0]), "=r"(r[1]), "=r"(r[2]), "=r"(r[3]) : "r"(a));
}
__device__ __forceinline__ void mma16816(float* c, const unsigned* a, const unsigned* b) {
    asm volatile(
        "mma.sync.aligned.m16n8k16.row.col.f32.f16.f16.f32 "
        "{%0,%1,%2,%3},{%4,%5,%6,%7},{%8,%9},{%0,%1,%2,%3};"
        : "+f"(c[0]), "+f"(c[1]), "+f"(c[2]), "+f"(c[3])
        : "r"(a[0]), "r"(a[1]), "r"(a[2]), "r"(a[3]), "r"(b[0]), "r"(b[1]));
}
__device__ __forceinline__ void cp16(unsigned dst, const void* src) {
    asm volatile("cp.async.cg.shared.global [%0],[%1],16;" :: "r"(dst), "l"(src));
}
#define CP_COMMIT() asm volatile("cp.async.commit_group;")
#define CP_WAIT1()  asm volatile("cp.async.wait_group 1;")
#define CP_WAIT0()  asm volatile("cp.async.wait_group 0;")

__device__ __forceinline__ unsigned pack2(float x, float y) {
    __half2 h = __floats2half2_rn(x, y);
    return *reinterpret_cast<unsigned*>(&h);
}

// ---------------------------------------------------------------------------
// fp32 -> fp16 conversion (memory-bound)
// ---------------------------------------------------------------------------
__global__ __launch_bounds__(256) void cvt_kernel(
    const float* __restrict__ in, __half* __restrict__ out, int n)
{
    int i = (blockIdx.x * 256 + threadIdx.x) * 4;
    if (i >= n) return;
    float4 v = *(const float4*)(in + i);
    *(unsigned*)(out + i)     = pack2(v.x, v.y);
    *(unsigned*)(out + i + 2) = pack2(v.z, v.w);
}

// ---------------------------------------------------------------------------
// fp16 tensor-core GEMM: C[8192,1024] = A[8192,1024] @ W[1024,1024] + bias
// BM=BN=128, BK=32, 256 thr (8 warps 2x4), warp tile 64x32, double-buffered.
// MODE 1: fp16 out, head-split [B,H,S,HD], value scaled. MODE 0: fp32 row-major.
// ---------------------------------------------------------------------------
#define GBM 128
#define GBN 128
#define GBK 32
#define ASTR 40
#define BSTR 136
#define A_STAGE (GBM * ASTR)   // 5120 halfs
#define B_STAGE (GBK * BSTR)   // 4352 halfs

template <int MODE>
__global__ __launch_bounds__(256) void gemm_h(
    const __half* __restrict__ Ag, const __half* __restrict__ Wg,
    const float* __restrict__ bias, float scale,
    float* __restrict__ Cf, __half* __restrict__ Ch)
{
    __shared__ __half sA[2 * A_STAGE];
    __shared__ __half sB[2 * B_STAGE];

    const int tid = threadIdx.x;
    const int lane = tid & 31, warp = tid >> 5;
    const int wm = (warp >> 2) * 64;
    const int wn = (warp & 3) * 32;
    const int m0 = blockIdx.y * GBM;
    const int n0 = blockIdx.x * GBN;
    const unsigned sAb = smem_u32(sA), sBb = smem_u32(sB);

    float acc[4][4][4];
    #pragma unroll
    for (int i = 0; i < 4; i++)
        #pragma unroll
        for (int j = 0; j < 4; j++)
            #pragma unroll
            for (int r = 0; r < 4; r++) acc[i][j][r] = 0.0f;

    auto load_stage = [&](int st, int k0) {
        #pragma unroll
        for (int c = 0; c < 2; c++) {
            int id = tid + c * 256;
            int row = id >> 2, col = (id & 3) * 8;
            cp16(sAb + (st * A_STAGE + row * ASTR + col) * 2,
                 Ag + (size_t)(m0 + row) * DM + k0 + col);
        }
        #pragma unroll
        for (int c = 0; c < 2; c++) {
            int id = tid + c * 256;
            int row = id >> 4, col = (id & 15) * 8;
            cp16(sBb + (st * B_STAGE + row * BSTR + col) * 2,
                 Wg + (size_t)(k0 + row) * DM + n0 + col);
        }
    };

    load_stage(0, 0);
    CP_COMMIT();

    const int NIT = DM / GBK;  // 32
    for (int it = 0; it < NIT; it++) {
        const int st = it & 1;
        if (it + 1 < NIT) { load_stage(st ^ 1, (it + 1) * GBK); CP_COMMIT(); CP_WAIT1(); }
        else              { CP_WAIT0(); }
        __syncthreads();

        #pragma unroll
        for (int kk = 0; kk < 2; kk++) {
            unsigned b[4][2];
            #pragma unroll
            for (int nt2 = 0; nt2 < 2; nt2++) {
                unsigned r[4];
                ldsm4t(r, sBb + (st * B_STAGE + (kk * 16 + (lane & 15)) * BSTR
                                 + wn + nt2 * 16 + ((lane >> 4) & 1) * 8) * 2);
                b[2 * nt2][0] = r[0]; b[2 * nt2][1] = r[1];
                b[2 * nt2 + 1][0] = r[2]; b[2 * nt2 + 1][1] = r[3];
            }
            #pragma unroll
            for (int mt = 0; mt < 4; mt++) {
                unsigned a[4];
                ldsm4(a, sAb + (st * A_STAGE + (wm + mt * 16 + (lane & 15)) * ASTR
                                + kk * 16 + ((lane >> 4) & 1) * 8) * 2);
                #pragma unroll
                for (int nt = 0; nt < 4; nt++) mma16816(acc[mt][nt], a, b[nt]);
            }
        }
        __syncthreads();
    }

    const int g = lane >> 2, tg = lane & 3;
    #pragma unroll
    for (int mt = 0; mt < 4; mt++) {
        const int r = m0 + wm + mt * 16 + g;
        #pragma unroll
        for (int nt = 0; nt < 4; nt++) {
            const int col = n0 + wn + nt * 8 + 2 * tg;
            const float2 bv = *(const float2*)&bias[col];
            float v00 = (acc[mt][nt][0] + bv.x) * scale;
            float v01 = (acc[mt][nt][1] + bv.y) * scale;
            float v10 = (acc[mt][nt][2] + bv.x) * scale;
            float v11 = (acc[mt][nt][3] + bv.y) * scale;
            if (MODE == 0) {
                *(float2*)&Cf[(size_t)r * DM + col]       = make_float2(v00, v01);
                *(float2*)&Cf[(size_t)(r + 8) * DM + col] = make_float2(v10, v11);
            } else {
                const int h = col >> 6, d = col & 63;
                int bb = r >> 11, ss = r & 2047;
                *(unsigned*)&Ch[(((size_t)(bb * NH + h) * SEQ) + ss) * HD + d] = pack2(v00, v01);
                bb = (r + 8) >> 11; ss = (r + 8) & 2047;
                *(unsigned*)&Ch[(((size_t)(bb * NH + h) * SEQ) + ss) * HD + d] = pack2(v10, v11);
            }
        }
    }
}

// ---------------------------------------------------------------------------
// FlashAttention-2, fp16 mma. Block = 128 thr (4 warps), 64 q rows/block.
// Each warp owns 16 q rows end-to-end. K/V double-buffered via cp.async.
// Q pre-scaled by 1/8. Writes fp16 [B,S,DM].
// ---------------------------------------------------------------------------
#define ATS 64
#define KSTR 72
#define KV_STAGE (ATS * KSTR)   // 4608 halfs

__global__ __launch_bounds__(128) void attn_fa(
    const __half* __restrict__ Q, const __half* __restrict__ K,
    const __half* __restrict__ V, __half* __restrict__ Out)
{
    __shared__ __half sK[2 * KV_STAGE];
    __shared__ __half sV[2 * KV_STAGE];

    const int bh = blockIdx.y;
    const int q0 = blockIdx.x * ATS;
    const int tid = threadIdx.x;
    const int warp = tid >> 5, lane = tid & 31;
    const int g = lane >> 2, tg = lane & 3;
    const size_t base = (size_t)bh * SEQ * HD;
    const unsigned sKb = smem_u32(sK), sVb = smem_u32(sV);

    // Q fragments in registers for whole kernel: 4 k-steps x 4 regs
    unsigned qf[4][4];
    {
        const int r0 = q0 + warp * 16;
        #pragma unroll
        for (int kk = 0; kk < 4; kk++) {
            const size_t i0 = base + (size_t)(r0 + g) * HD + kk * 16 + 2 * tg;
            const size_t i1 = base + (size_t)(r0 + g + 8) * HD + kk * 16 + 2 * tg;
            qf[kk][0] = *(const unsigned*)(Q + i0);
            qf[kk][1] = *(const unsigned*)(Q + i1);
            qf[kk][2] = *(const unsigned*)(Q + i0 + 8);
            qf[kk][3] = *(const unsigned*)(Q + i1 + 8);
        }
    }

    auto load_kv = [&](int st, int kv0) {
        #pragma unroll
        for (int c = 0; c < 4; c++) {
            int id = tid + c * 128;
            int row = id >> 3, col = (id & 7) * 8;
            size_t src = base + (size_t)(kv0 + row) * HD + col;
            unsigned off = (st * KV_STAGE + row * KSTR + col) * 2;
            cp16(sKb + off, K + src);
            cp16(sVb + off, V + src);
        }
    };

    float o[8][4];
    #pragma unroll
    for (int i = 0; i < 8; i++)
        #pragma unroll
        for (int j = 0; j < 4; j++) o[i][j] = 0.0f;
    float m0 = -1e30f, m1 = -1e30f, l0 = 0.0f, l1 = 0.0f;

    load_kv(0, 0);
    CP_COMMIT();

    const int NKV = SEQ / ATS;  // 32
    for (int it = 0; it < NKV; it++) {
        const int st = it & 1;
        if (it + 1 < NKV) { load_kv(st ^ 1, (it + 1) * ATS); CP_COMMIT(); CP_WAIT1(); }
        else              { CP_WAIT0(); }
        __syncthreads();

        // ---- S = Q @ K^T : s[8 ntiles][4] fp32
        float s[8][4];
        #pragma unroll
        for (int i = 0; i < 8; i++)
            #pragma unroll
            for (int j = 0; j < 4; j++) s[i][j] = 0.0f;

        #pragma unroll
        for (int kk = 0; kk < 4; kk++) {
            #pragma unroll
            for (int nt2 = 0; nt2 < 4; nt2++) {
                unsigned r[4];
                ldsm4(r, sKb + (st * KV_STAGE
                                + (nt2 * 16 + ((lane >> 4) << 3) + (lane & 7)) * KSTR
                                + kk * 16 + ((lane >> 3) & 1) * 8) * 2);
                mma16816(s[2 * nt2],     qf[kk], r);
                mma16816(s[2 * nt2 + 1], qf[kk], r + 2);
            }
        }

        // ---- online softmax (rows g and g+8)
        float mx0 = -1e30f, mx1 = -1e30f;
        #pragma unroll
        for (int nt = 0; nt < 8; nt++) {
            mx0 = fmaxf(mx0, fmaxf(s[nt][0], s[nt][1]));
            mx1 = fmaxf(mx1, fmaxf(s[nt][2], s[nt][3]));
        }
        mx0 = fmaxf(mx0, __shfl_xor_sync(~0u, mx0, 1));
        mx0 = fmaxf(mx0, __shfl_xor_sync(~0u, mx0, 2));
        mx1 = fmaxf(mx1, __shfl_xor_sync(~0u, mx1, 1));
        mx1 = fmaxf(mx1, __shfl_xor_sync(~0u, mx1, 2));
        const float mn0 = fmaxf(m0, mx0), mn1 = fmaxf(m1, mx1);
        const float c0 = __expf(m0 - mn0), c1 = __expf(m1 - mn1);
        m0 = mn0; m1 = mn1;

        float ps0 = 0.f, ps1 = 0.f;
        #pragma unroll
        for (int nt = 0; nt < 8; nt++) {
            s[nt][0] = __expf(s[nt][0] - mn0);
            s[nt][1] = __expf(s[nt][1] - mn0);
            s[nt][2] = __expf(s[nt][2] - mn1);
            s[nt][3] = __expf(s[nt][3] - mn1);
            ps0 += s[nt][0] + s[nt][1];
            ps1 += s[nt][2] + s[nt][3];
        }
        ps0 += __shfl_xor_sync(~0u, ps0, 1); ps0 += __shfl_xor_sync(~0u, ps0, 2);
        ps1 += __shfl_xor_sync(~0u, ps1, 1); ps1 += __shfl_xor_sync(~0u, ps1, 2);
        l0 = l0 * c0 + ps0;
        l1 = l1 * c1 + ps1;

        #pragma unroll
        for (int nt = 0; nt < 8; nt++) {
            o[nt][0] *= c0; o[nt][1] *= c0; o[nt][2] *= c1; o[nt][3] *= c1;
        }

        // ---- P fragments (fp16) from S fragments: pa[kk] covers S ntiles 2kk,2kk+1
        unsigned pa[4][4];
        #pragma unroll
        for (int kk = 0; kk < 4; kk++) {
            pa[kk][0] = pack2(s[2 * kk][0],     s[2 * kk][1]);
            pa[kk][1] = pack2(s[2 * kk][2],     s[2 * kk][3]);
            pa[kk][2] = pack2(s[2 * kk + 1][0], s[2 * kk + 1][1]);
            pa[kk][3] = pack2(s[2 * kk + 1][2], s[2 * kk + 1][3]);
        }

        // ---- O += P @ V
        #pragma unroll
        for (int kk = 0; kk < 4; kk++) {
            #pragma unroll
            for (int nt2 = 0; nt2 < 4; nt2++) {
                unsigned r[4];
                ldsm4t(r, sVb + (st * KV_STAGE + (kk * 16 + (lane & 15)) * KSTR
                                 + nt2 * 16 + ((lane >> 4) & 1) * 8) * 2);
                mma16816(o[2 * nt2],     pa[kk], r);
                mma16816(o[2 * nt2 + 1], pa[kk], r + 2);
            }
        }
        __syncthreads();
    }

    // ---- write out [B,S,DM] fp16
    const float i0 = 1.0f / l0, i1 = 1.0f / l1;
    const int b = bh / NH, h = bh % NH;
    const size_t tok = (size_t)b * SEQ + q0 + warp * 16 + g;
    #pragma unroll
    for (int nt = 0; nt < 8; nt++) {
        const int col = h * HD + nt * 8 + 2 * tg;
        *(unsigned*)&Out[tok * DM + col]       = pack2(o[nt][0] * i0, o[nt][1] * i0);
        *(unsigned*)&Out[(tok + 8) * DM + col] = pack2(o[nt][2] * i1, o[nt][3] * i1);
    }
}

// ---------------------------------------------------------------------------
// Residual + LayerNorm (one 256-thr block per token row)
// ---------------------------------------------------------------------------
__global__ __launch_bounds__(256) void ln_kernel(
    const float* __restrict__ X, const float* __restrict__ P,
    const float* __restrict__ gamma, const float* __restrict__ beta,
    float* __restrict__ out)
{
    const int r = blockIdx.x, t = threadIdx.x;
    const float4 x4 = ((const float4*)(X + (size_t)r * DM))[t];
    const float4 p4 = ((const float4*)(P + (size_t)r * DM))[t];
    float v0 = x4.x + p4.x, v1 = x4.y + p4.y, v2 = x4.z + p4.z, v3 = x4.w + p4.w;

    __shared__ float red[8];
    __shared__ float s_mu, s_rstd;

    float s = v0 + v1 + v2 + v3;
    #pragma unroll
    for (int off = 16; off > 0; off >>= 1) s += __shfl_xor_sync(~0u, s, off);
    if ((t & 31) == 0) red[t >> 5] = s;
    __syncthreads();
    if (t == 0) {
        float tot = 0.f;
        #pragma unroll
        for (int i = 0; i < 8; i++) tot += red[i];
        s_mu = tot * (1.0f / DM);
    }
    __syncthreads();
    const float mu = s_mu;
    float d0 = v0 - mu, d1 = v1 - mu, d2 = v2 - mu, d3 = v3 - mu;
    float sq = d0 * d0 + d1 * d1 + d2 * d2 + d3 * d3;
    #pragma unroll
    for (int off = 16; off > 0; off >>= 1) sq += __shfl_xor_sync(~0u, sq, off);
    if ((t & 31) == 0) red[t >> 5] = sq;
    __syncthreads();
    if (t == 0) {
        float tot = 0.f;
        #pragma unroll
        for (int i = 0; i < 8; i++) tot += red[i];
        s_rstd = rsqrtf(tot * (1.0f / DM) + LN_EPS);
    }
    __syncthreads();
    const float rstd = s_rstd;

    const float4 g4 = ((const float4*)gamma)[t];
    const float4 b4 = ((const float4*)beta)[t];
    float4 o4;
    o4.x = d0 * rstd * g4.x + b4.x;
    o4.y = d1 * rstd * g4.y + b4.y;
    o4.z = d2 * rstd * g4.z + b4.z;
    o4.w = d3 * rstd * g4.w + b4.w;
    ((float4*)(out + (size_t)r * DM))[t] = o4;
}

// ---------------------------------------------------------------------------
// Launch
// ---------------------------------------------------------------------------
extern "C" void kernel_launch(void* const* d_in, const int* in_sizes, int n_in,
                              void* d_out, int out_size)
{
    const float* x     = (const float*)d_in[0];
    const float* Wq    = (const float*)d_in[1];
    const float* bq    = (const float*)d_in[2];
    const float* Wk    = (const float*)d_in[3];
    const float* bk    = (const float*)d_in[4];
    const float* Wv    = (const float*)d_in[5];
    const float* bv    = (const float*)d_in[6];
    const float* Wo    = (const float*)d_in[7];
    const float* bo    = (const float*)d_in[8];
    const float* gamma = (const float*)d_in[9];
    const float* beta  = (const float*)d_in[10];
    float* out = (float*)d_out;

    __half *hx, *hwq, *hwk, *hwv, *hwo, *q, *k, *v, *ah;
    float *proj;
    cudaGetSymbolAddress((void**)&hx,  g_hx);
    cudaGetSymbolAddress((void**)&hwq, g_hwq);
    cudaGetSymbolAddress((void**)&hwk, g_hwk);
    cudaGetSymbolAddress((void**)&hwv, g_hwv);
    cudaGetSymbolAddress((void**)&hwo, g_hwo);
    cudaGetSymbolAddress((void**)&q,   g_q);
    cudaGetSymbolAddress((void**)&k,   g_k);
    cudaGetSymbolAddress((void**)&v,   g_v);
    cudaGetSymbolAddress((void**)&ah,  g_ah);
    cudaGetSymbolAddress((void**)&proj, g_proj);

    cvt_kernel<<<NTOK * DM / 1024, 256>>>(x, hx, NTOK * DM);
    cvt_kernel<<<DM * DM / 1024, 256>>>(Wq, hwq, DM * DM);
    cvt_kernel<<<DM * DM / 1024, 256>>>(Wk, hwk, DM * DM);
    cvt_kernel<<<DM * DM / 1024, 256>>>(Wv, hwv, DM * DM);
    cvt_kernel<<<DM * DM / 1024, 256>>>(Wo, hwo, DM * DM);

    dim3 ggrid(DM / GBN, NTOK / GBM);   // (8, 64)
    gemm_h<1><<<ggrid, 256>>>(hx, hwq, bq, 0.125f, nullptr, q);  // 1/sqrt(64) folded in
    gemm_h<1><<<ggrid, 256>>>(hx, hwk, bk, 1.0f,   nullptr, k);
    gemm_h<1><<<ggrid, 256>>>(hx, hwv, bv, 1.0f,   nullptr, v);

    attn_fa<<<dim3(SEQ / ATS, BATCH * NH), 128>>>(q, k, v, ah);

    gemm_h<0><<<ggrid, 256>>>(ah, hwo, bo, 1.0f, proj, nullptr);

    ln_kernel<<<NTOK, 256>>>(x, proj, gamma, beta, out);
}